// round 4
// baseline (speedup 1.0000x reference)
#include <cuda_runtime.h>
#include <math.h>

#define N_NODES 100000
#define N_EDGES 3200000
#define F_IN 25
#define F_HID 16
#define F_OUT 2

// Scratch (allocation-free rule: __device__ globals)
__device__ float g_deg[N_NODES];
__device__ float g_dinv[N_NODES];
__device__ float g_hs1[N_NODES * F_HID];   // (x@W1) * dinv[i], pre-scaled
__device__ float g_acc1[N_NODES * F_HID];  // edge-scattered sums
__device__ float g_hs2[N_NODES * F_OUT];   // (relu(layer1)@W2) * dinv[i]
__device__ float g_acc2[N_NODES * F_OUT];
__device__ int   g_is64;                   // 1 if edge_index is int64, 0 if int32

// ---------------------------------------------------------------------------
__device__ __forceinline__ void red_add_v4(float* p, float a, float b, float c, float d) {
    asm volatile("red.global.add.v4.f32 [%0], {%1, %2, %3, %4};"
                 :: "l"(p), "f"(a), "f"(b), "f"(c), "f"(d) : "memory");
}
__device__ __forceinline__ void red_add_v2(float* p, float a, float b) {
    asm volatile("red.global.add.v2.f32 [%0], {%1, %2};"
                 :: "l"(p), "f"(a), "f"(b) : "memory");
}

// ---------------------------------------------------------------------------
// Zero scratch + detect edge_index dtype (int64 => odd 32-bit words all zero).
__global__ void k_zero_detect(const unsigned int* __restrict__ ei_w) {
    int stride = gridDim.x * blockDim.x;
    int tid = blockIdx.x * blockDim.x + threadIdx.x;
    for (int i = tid; i < N_NODES * F_HID; i += stride) g_acc1[i] = 0.0f;
    for (int i = tid; i < N_NODES * F_OUT; i += stride) g_acc2[i] = 0.0f;
    for (int i = tid; i < N_NODES; i += stride) g_deg[i] = 0.0f;

    if (blockIdx.x == 0) {
        __shared__ int nonzero;
        if (threadIdx.x == 0) nonzero = 0;
        __syncthreads();
        int nz = 0;
        for (int i = threadIdx.x; i < 2048; i += blockDim.x)
            if (ei_w[2 * i + 1] != 0u) nz = 1;
        if (nz) atomicOr(&nonzero, 1);
        __syncthreads();
        if (threadIdx.x == 0) g_is64 = (nonzero == 0) ? 1 : 0;
    }
}

// Load 2 consecutive edge values (e0 even) from row or col half.
__device__ __forceinline__ void load2(const void* ei, int base, int e0, int& v0, int& v1) {
    if (g_is64) {
        longlong2 v = __ldg((const longlong2*)((const long long*)ei + base + e0));
        v0 = (int)v.x; v1 = (int)v.y;
    } else {
        int2 v = __ldg((const int2*)((const int*)ei + base + e0));
        v0 = v.x; v1 = v.y;
    }
}

// Degree: count incoming edges per target (2 edges/thread).
__global__ void k_degree(const void* __restrict__ ei) {
    int e0 = 2 * (blockIdx.x * blockDim.x + threadIdx.x);
    if (e0 >= N_EDGES) return;
    int c0, c1;
    load2(ei, N_EDGES, e0, c0, c1);
    atomicAdd(&g_deg[c0], 1.0f);
    atomicAdd(&g_deg[c1], 1.0f);
}

// Layer-1 transform fused with dinv: hs1[i] = (x[i] @ W1) * dinv[i]
// x staged through smem for coalescing (row stride 25 floats).
__global__ void k_xform1(const float* __restrict__ x, const float* __restrict__ W1) {
    __shared__ float sW1[F_IN * F_HID];
    __shared__ float sx[256 * F_IN];
    for (int i = threadIdx.x; i < F_IN * F_HID; i += blockDim.x)
        sW1[i] = W1[i];

    int base_node = blockIdx.x * 256;
    int nvals = min(256, N_NODES - base_node) * F_IN;
    const float* xblk = x + base_node * F_IN;
    for (int j = threadIdx.x; j < nvals; j += blockDim.x)
        sx[j] = xblk[j];
    __syncthreads();

    int i = base_node + threadIdx.x;
    if (i >= N_NODES) return;

    float di = rsqrtf(g_deg[i] + 1.0f);  // +1 self-loop
    g_dinv[i] = di;

    const float* xi = &sx[threadIdx.x * F_IN];
    float acc[F_HID];
#pragma unroll
    for (int f = 0; f < F_HID; f++) acc[f] = 0.0f;
#pragma unroll
    for (int k = 0; k < F_IN; k++) {
        float xv = xi[k];
#pragma unroll
        for (int f = 0; f < F_HID; f++) acc[f] += xv * sW1[k * F_HID + f];
    }

    float4* out = (float4*)&g_hs1[i * F_HID];
#pragma unroll
    for (int q = 0; q < 4; q++) {
        float4 v;
        v.x = acc[q * 4 + 0] * di;
        v.y = acc[q * 4 + 1] * di;
        v.z = acc[q * 4 + 2] * di;
        v.w = acc[q * 4 + 3] * di;
        out[q] = v;
    }
}

// Layer-1 edge scatter: acc1[col] += hs1[row]  (2 edges/thread, v4 reds)
__global__ void k_scatter1(const void* __restrict__ ei) {
    int e0 = 2 * (blockIdx.x * blockDim.x + threadIdx.x);
    if (e0 >= N_EDGES) return;
    int r0, r1, c0, c1;
    load2(ei, 0, e0, r0, r1);
    load2(ei, N_EDGES, e0, c0, c1);

    const float4* s0 = (const float4*)&g_hs1[r0 * F_HID];
    const float4* s1 = (const float4*)&g_hs1[r1 * F_HID];
    float4 a0 = __ldg(s0 + 0), a1 = __ldg(s0 + 1), a2 = __ldg(s0 + 2), a3 = __ldg(s0 + 3);
    float4 b0 = __ldg(s1 + 0), b1 = __ldg(s1 + 1), b2 = __ldg(s1 + 2), b3 = __ldg(s1 + 3);

    float* d0 = &g_acc1[c0 * F_HID];
    float* d1 = &g_acc1[c1 * F_HID];
    red_add_v4(d0 + 0,  a0.x, a0.y, a0.z, a0.w);
    red_add_v4(d0 + 4,  a1.x, a1.y, a1.z, a1.w);
    red_add_v4(d0 + 8,  a2.x, a2.y, a2.z, a2.w);
    red_add_v4(d0 + 12, a3.x, a3.y, a3.z, a3.w);
    red_add_v4(d1 + 0,  b0.x, b0.y, b0.z, b0.w);
    red_add_v4(d1 + 4,  b1.x, b1.y, b1.z, b1.w);
    red_add_v4(d1 + 8,  b2.x, b2.y, b2.z, b2.w);
    red_add_v4(d1 + 12, b3.x, b3.y, b3.z, b3.w);
}

// Finalize layer 1 (+ self loop, bias, relu) then transform 2:
// hs2[i] = (relu((acc1[i]+hs1[i])*dinv[i] + b1) @ W2) * dinv[i]
__global__ void k_fin1_xform2(const float* __restrict__ b1,
                              const float* __restrict__ W2) {
    __shared__ float sW2[F_HID * F_OUT];
    __shared__ float sb1[F_HID];
    if (threadIdx.x < F_HID * F_OUT) sW2[threadIdx.x] = W2[threadIdx.x];
    if (threadIdx.x < F_HID) sb1[threadIdx.x] = b1[threadIdx.x];
    __syncthreads();

    int i = blockIdx.x * blockDim.x + threadIdx.x;
    if (i >= N_NODES) return;

    float di = g_dinv[i];
    const float4* a = (const float4*)&g_acc1[i * F_HID];
    const float4* h = (const float4*)&g_hs1[i * F_HID];
    float v[F_HID];
#pragma unroll
    for (int q = 0; q < 4; q++) {
        float4 av = a[q];
        float4 hv = h[q];
        v[q * 4 + 0] = (av.x + hv.x) * di + sb1[q * 4 + 0];
        v[q * 4 + 1] = (av.y + hv.y) * di + sb1[q * 4 + 1];
        v[q * 4 + 2] = (av.z + hv.z) * di + sb1[q * 4 + 2];
        v[q * 4 + 3] = (av.w + hv.w) * di + sb1[q * 4 + 3];
    }
#pragma unroll
    for (int f = 0; f < F_HID; f++) v[f] = fmaxf(v[f], 0.0f);

    float o0 = 0.0f, o1 = 0.0f;
#pragma unroll
    for (int f = 0; f < F_HID; f++) {
        o0 += v[f] * sW2[f * F_OUT + 0];
        o1 += v[f] * sW2[f * F_OUT + 1];
    }
    g_hs2[i * F_OUT + 0] = o0 * di;
    g_hs2[i * F_OUT + 1] = o1 * di;
}

// Layer-2 edge scatter: acc2[col] += hs2[row]  (2 edges/thread, v2 reds)
__global__ void k_scatter2(const void* __restrict__ ei) {
    int e0 = 2 * (blockIdx.x * blockDim.x + threadIdx.x);
    if (e0 >= N_EDGES) return;
    int r0, r1, c0, c1;
    load2(ei, 0, e0, r0, r1);
    load2(ei, N_EDGES, e0, c0, c1);
    float2 v0 = __ldg((const float2*)&g_hs2[r0 * F_OUT]);
    float2 v1 = __ldg((const float2*)&g_hs2[r1 * F_OUT]);
    red_add_v2(&g_acc2[c0 * F_OUT], v0.x, v0.y);
    red_add_v2(&g_acc2[c1 * F_OUT], v1.x, v1.y);
}

// Finalize layer 2 + log_softmax
__global__ void k_fin2(const float* __restrict__ b2, float* __restrict__ out) {
    int i = blockIdx.x * blockDim.x + threadIdx.x;
    if (i >= N_NODES) return;
    float di = g_dinv[i];
    float b20 = b2[0], b21 = b2[1];
    float o0 = (g_acc2[i * F_OUT + 0] + g_hs2[i * F_OUT + 0]) * di + b20;
    float o1 = (g_acc2[i * F_OUT + 1] + g_hs2[i * F_OUT + 1]) * di + b21;
    float m = fmaxf(o0, o1);
    float lse = m + logf(expf(o0 - m) + expf(o1 - m));
    float2 r;
    r.x = o0 - lse;
    r.y = o1 - lse;
    *(float2*)&out[i * F_OUT] = r;
}

// ---------------------------------------------------------------------------
extern "C" void kernel_launch(void* const* d_in, const int* in_sizes, int n_in,
                              void* d_out, int out_size) {
    const float* x = (const float*)d_in[0];
    const void* ei = d_in[1];
    const float* W1 = (const float*)d_in[2];
    const float* b1 = (const float*)d_in[3];
    const float* W2 = (const float*)d_in[4];
    const float* b2 = (const float*)d_in[5];
    float* out = (float*)d_out;

    const int TB = 256;
    int nblk_node = (N_NODES + TB - 1) / TB;
    int nblk_edge2 = (N_EDGES / 2 + TB - 1) / TB;

    k_zero_detect<<<592, TB>>>((const unsigned int*)ei);
    k_degree<<<nblk_edge2, TB>>>(ei);
    k_xform1<<<nblk_node, TB>>>(x, W1);
    k_scatter1<<<nblk_edge2, TB>>>(ei);
    k_fin1_xform2<<<nblk_node, TB>>>(b1, W2);
    k_scatter2<<<nblk_edge2, TB>>>(ei);
    k_fin2<<<nblk_node, TB>>>(b2, out);
}